// round 8
// baseline (speedup 1.0000x reference)
#include <cuda_runtime.h>
#include <cuda_bf16.h>
#include <mma.h>
#include <cstdint>

using namespace nvcuda;

#define N_NODES 50000
#define N_EDGES 500000
#define IN_CH   128
#define QKVC    256        // OUT_CH * HEADS
#define OUTC    64
#define HEADS   4
#define N_PAD   50048      // 391*128 = 782*64
#define LOGIT_BLOCKS (N_EDGES / 8)   // 62500, exact
#define M_TILES (N_PAD / 128)        // 391

// ---------------- scratch (device globals; no allocation allowed) ----------
__device__ float g_Q[(size_t)N_PAD * QKVC];
__device__ float g_K[(size_t)N_PAD * QKVC];
__device__ float g_V[(size_t)N_PAD * QKVC];
__device__ float g_agg[(size_t)N_PAD * QKVC];
__device__ float g_logit[(size_t)N_EDGES * HEADS];
__device__ float g_blockmax[LOGIT_BLOCKS * HEADS];
__device__ float g_max[HEADS];
__device__ float g_sum[HEADS];
__device__ int   g_idx64;

// CSR-by-target structures
__device__ int    g_deg[N_PAD];
__device__ int    g_pos[N_PAD];
__device__ int    g_off[N_PAD + 1];
__device__ int    g_csr_src[N_EDGES];
__device__ __align__(16) float g_csr_attn[(size_t)N_EDGES * HEADS];  // normalized attn

// split-bf16 operands for the HMMA path
__device__ __align__(16) uint4 g_xhi[(size_t)N_PAD * 16];   // [N_PAD][128] bf16 rows, 8 per uint4
__device__ __align__(16) uint4 g_xlo[(size_t)N_PAD * 16];
__device__ __align__(16) uint4 g_Wt[3 * 2 * 256 * 16];      // [w][hi/lo][n=256][k=128] bf16 (W^T)

// ---------------- helpers --------------------------------------------------
__device__ __forceinline__ void load_edge(const void* ei_raw, int e, int idx64,
                                          int& s, int& t) {
    if (idx64) {
        const long long* p = (const long long*)ei_raw;
        s = (int)p[e];
        t = (int)p[N_EDGES + e];
    } else {
        const int* p = (const int*)ei_raw;
        s = p[e];
        t = p[N_EDGES + e];
    }
}
__device__ __forceinline__ int load_tgt(const void* ei_raw, int e, int idx64) {
    if (idx64) return (int)((const long long*)ei_raw)[N_EDGES + e];
    return ((const int*)ei_raw)[N_EDGES + e];
}

// ---------------- 0: dtype sniff + zero small scratch ----------------------
__global__ void detect_idx_kernel(const int* ei32) {
    if (blockIdx.x == 0 && threadIdx.x == 0) {
        int zeros = 0;
        for (int i = 0; i < 64; i++)
            if (ei32[2 * i + 1] == 0) zeros++;
        g_idx64 = (zeros >= 60) ? 1 : 0;
    }
}
__global__ void zero_small_kernel() {
    int i = blockIdx.x * 256 + threadIdx.x;
    if (i < N_PAD) { g_deg[i] = 0; g_pos[i] = 0; }
    if (i < HEADS) g_sum[i] = 0.f;
}

// ---------------- 1a: split x -> bf16 hi/lo ---------------------------------
__global__ void __launch_bounds__(256) prep_x_kernel(const float* __restrict__ x) {
    int t = blockIdx.x * 256 + threadIdx.x;       // one per 8-float chunk
    if (t >= N_PAD * 16) return;
    int r = t >> 4, c8 = t & 15;
    float v[8];
    if (r < N_NODES) {
        float4 a = *(const float4*)&x[(size_t)r * IN_CH + c8 * 8];
        float4 b = *(const float4*)&x[(size_t)r * IN_CH + c8 * 8 + 4];
        v[0] = a.x; v[1] = a.y; v[2] = a.z; v[3] = a.w;
        v[4] = b.x; v[5] = b.y; v[6] = b.z; v[7] = b.w;
    } else {
#pragma unroll
        for (int j = 0; j < 8; j++) v[j] = 0.f;
    }
    union { __nv_bfloat16 h[8]; uint4 u; } hi, lo;
#pragma unroll
    for (int j = 0; j < 8; j++) {
        __nv_bfloat16 h = __float2bfloat16_rn(v[j]);
        hi.h[j] = h;
        lo.h[j] = __float2bfloat16_rn(v[j] - __bfloat162float(h));
    }
    g_xhi[t] = hi.u;
    g_xlo[t] = lo.u;
}

// ---------------- 1b: W^T hi/lo images ([n][k] row-major bf16) --------------
__global__ void __launch_bounds__(256) prep_w_kernel(
    const float* __restrict__ Wq, const float* __restrict__ Wk,
    const float* __restrict__ Wv) {
    int t = blockIdx.x * 256 + threadIdx.x;       // 3*256*16 = 12288 (w, n, k8)
    if (t >= 3 * 256 * 16) return;
    int w = t >> 12;
    int n = (t >> 4) & 255;
    int k8 = t & 15;
    const float* W = (w == 0) ? Wq : (w == 1) ? Wk : Wv;
    union { __nv_bfloat16 h[8]; uint4 u; } hi, lo;
#pragma unroll
    for (int j = 0; j < 8; j++) {
        float v = W[(size_t)(k8 * 8 + j) * QKVC + n];
        __nv_bfloat16 h = __float2bfloat16_rn(v);
        hi.h[j] = h;
        lo.h[j] = __float2bfloat16_rn(v - __bfloat162float(h));
    }
    g_Wt[((w * 2 + 0) * 256 + n) * 16 + k8] = hi.u;
    g_Wt[((w * 2 + 1) * 256 + n) * 16 + k8] = lo.u;
}

// ---------------- 1c: QKV GEMM via wmma bf16 (3-term split, fp32 acc) -------
// grid (391, 2). A hi/lo staged in SMEM (70KB -> 2-3 CTA/SM); B fragments
// loaded directly from global (L1-resident 32KB images shared by all CTAs).
#define LDA 136                                    // padded ld (elements)
static constexpr int SA_HI = 0;
static constexpr int SA_LO = 128 * LDA * 2;        // 34816
static constexpr int SM_QKV = SA_LO + 128 * LDA * 2;  // 69632 bytes

__global__ void __launch_bounds__(256) qkv_wmma_kernel() {
    extern __shared__ __align__(16) char smem[];
    __nv_bfloat16* Ahi = (__nv_bfloat16*)(smem + SA_HI);
    __nv_bfloat16* Alo = (__nv_bfloat16*)(smem + SA_LO);

    int tid = threadIdx.x;
    int bx = blockIdx.x, by = blockIdx.y;
    int wid = tid >> 5;
    int wr = wid & 3;           // warp row (4 x 32 rows)
    int wc = wid >> 2;          // warp col (2 x 64 cols)

    // stage A hi/lo (128 rows x 128 k)
    for (int i = tid; i < 2048; i += 256) {
        int r = i >> 4, c8 = i & 15;
        size_t src = (size_t)(bx * 128 + r) * 16 + c8;
        *(uint4*)&Ahi[r * LDA + c8 * 8] = g_xhi[src];
        *(uint4*)&Alo[r * LDA + c8 * 8] = g_xlo[src];
    }
    __syncthreads();

    const __nv_bfloat16* Wg = (const __nv_bfloat16*)g_Wt;

    for (int z = 0; z < 3; z++) {
        wmma::fragment<wmma::accumulator, 16, 16, 16, float> acc[2][4];
#pragma unroll
        for (int i = 0; i < 2; i++)
#pragma unroll
            for (int j = 0; j < 4; j++) wmma::fill_fragment(acc[i][j], 0.f);

#pragma unroll
        for (int term = 0; term < 3; term++) {
            const __nv_bfloat16* Ap = (term == 2) ? Alo : Ahi;
            int bsel = (term == 1) ? 1 : 0;   // hi for terms 0,2; lo for term 1
            const __nv_bfloat16* Bg = Wg + (size_t)((z * 2 + bsel) * 256) * 128;
#pragma unroll
            for (int k0 = 0; k0 < 128; k0 += 16) {
                wmma::fragment<wmma::matrix_a, 16, 16, 16, __nv_bfloat16, wmma::row_major> a[2];
                wmma::load_matrix_sync(a[0], Ap + (wr * 32 + 0)  * LDA + k0, LDA);
                wmma::load_matrix_sync(a[1], Ap + (wr * 32 + 16) * LDA + k0, LDA);
#pragma unroll
                for (int j = 0; j < 4; j++) {
                    wmma::fragment<wmma::matrix_b, 16, 16, 16, __nv_bfloat16, wmma::col_major> b;
                    // col_major: B(k,n) = Bg[k + n*128]; rows of g_Wt are n with k contiguous
                    wmma::load_matrix_sync(b, Bg + (size_t)(by * 128 + wc * 64 + j * 16) * 128 + k0, 128);
                    wmma::mma_sync(acc[0][j], a[0], b, acc[0][j]);
                    wmma::mma_sync(acc[1][j], a[1], b, acc[1][j]);
                }
            }
        }

        float* C = (z == 0) ? g_Q : (z == 1) ? g_K : g_V;
        int row0 = bx * 128 + wr * 32;
        int col0 = by * 128 + wc * 64;
#pragma unroll
        for (int i = 0; i < 2; i++)
#pragma unroll
            for (int j = 0; j < 4; j++)
                wmma::store_matrix_sync(&C[(size_t)(row0 + i * 16) * QKVC + col0 + j * 16],
                                        acc[i][j], QKVC, wmma::mem_row_major);
    }
}

// ---------------- CSR build: histogram -> scan -> scatter -------------------
__global__ void __launch_bounds__(256) hist_kernel(const void* __restrict__ ei_raw) {
    int e = blockIdx.x * 256 + threadIdx.x;
    if (e >= N_EDGES) return;
    int t = load_tgt(ei_raw, e, g_idx64);
    atomicAdd(&g_deg[t], 1);
}

__global__ void __launch_bounds__(1024) scan_kernel() {
    const int CH = (N_PAD + 1023) / 1024;   // 49
    __shared__ int ssum[1024];
    int t = threadIdx.x;
    int base = t * CH;
    int s = 0;
    for (int i = 0; i < CH; i++) {
        int idx = base + i;
        if (idx < N_PAD) s += g_deg[idx];
    }
    ssum[t] = s;
    __syncthreads();
    for (int off = 1; off < 1024; off <<= 1) {
        int v = 0;
        if (t >= off) v = ssum[t - off];
        __syncthreads();
        ssum[t] += v;
        __syncthreads();
    }
    int run = ssum[t] - s;                  // exclusive base for this chunk
    for (int i = 0; i < CH; i++) {
        int idx = base + i;
        if (idx < N_PAD) { g_off[idx] = run; run += g_deg[idx]; }
    }
    if (t == 1023) g_off[N_PAD] = run;
}

// scatter: also pre-normalize attention into CSR order (g_sum must be ready)
__global__ void __launch_bounds__(256) scatter_kernel(const void* __restrict__ ei_raw) {
    int e = blockIdx.x * 256 + threadIdx.x;
    if (e >= N_EDGES) return;
    int s, t;
    load_edge(ei_raw, e, g_idx64, s, t);
    int slot = g_off[t] + atomicAdd(&g_pos[t], 1);
    g_csr_src[slot] = s;
    float4 ex = *(const float4*)&g_logit[(size_t)e * HEADS];
    float4 at = make_float4(ex.x / g_sum[0], ex.y / g_sum[1],
                            ex.z / g_sum[2], ex.w / g_sum[3]);
    *(float4*)&g_csr_attn[(size_t)slot * HEADS] = at;
}

// ---------------- 2: per-edge attention logits (warp per edge) -------------
__global__ void __launch_bounds__(256) edge_logits_kernel(
    const void* __restrict__ ei_raw,
    const float* __restrict__ ew,
    const float* __restrict__ We)
{
    __shared__ float wvals[8][HEADS];
    int wid = threadIdx.x >> 5;
    int lane = threadIdx.x & 31;
    int e = blockIdx.x * 8 + wid;
    int idx64 = g_idx64;

    int s, t;
    load_edge(ei_raw, e, idx64, s, t);

    const float4* q = (const float4*)(g_Q + (size_t)t * QKVC);
    const float4* k = (const float4*)(g_K + (size_t)s * QKVC);
    float4 q0 = q[lane * 2], q1 = q[lane * 2 + 1];
    float4 k0 = k[lane * 2], k1 = k[lane * 2 + 1];

    float ps = q0.x * k0.x + q0.y * k0.y + q0.z * k0.z + q0.w * k0.w
             + q1.x * k1.x + q1.y * k1.y + q1.z * k1.z + q1.w * k1.w;
    ps += __shfl_xor_sync(0xffffffffu, ps, 4);
    ps += __shfl_xor_sync(0xffffffffu, ps, 2);
    ps += __shfl_xor_sync(0xffffffffu, ps, 1);

    if ((lane & 7) == 0) {
        int h = lane >> 3;
        float logit = ps * 0.125f + ew[e] * We[h];
        logit = (logit > 0.f) ? logit : 0.2f * logit;
        g_logit[(size_t)e * HEADS + h] = logit;
        wvals[wid][h] = logit;
    }
    __syncthreads();
    if (threadIdx.x < HEADS) {
        float m = wvals[0][threadIdx.x];
#pragma unroll
        for (int w = 1; w < 8; w++) m = fmaxf(m, wvals[w][threadIdx.x]);
        g_blockmax[blockIdx.x * HEADS + threadIdx.x] = m;
    }
}

// ---------------- 3: global max per head -----------------------------------
__global__ void reduce_max_kernel() {
    int h = blockIdx.x;
    __shared__ float sm[256];
    float m = -3.4e38f;
    for (int i = threadIdx.x; i < LOGIT_BLOCKS; i += 256)
        m = fmaxf(m, g_blockmax[i * HEADS + h]);
    sm[threadIdx.x] = m;
    __syncthreads();
    for (int s = 128; s > 0; s >>= 1) {
        if (threadIdx.x < s) sm[threadIdx.x] = fmaxf(sm[threadIdx.x], sm[threadIdx.x + s]);
        __syncthreads();
    }
    if (threadIdx.x == 0) g_max[h] = sm[0];
}

// ---------------- 4: exp (in place) + per-head sum -------------------------
__global__ void __launch_bounds__(256) coef_kernel() {
    __shared__ float ssum[HEADS];
    if (threadIdx.x < HEADS) ssum[threadIdx.x] = 0.f;
    __syncthreads();

    int e = blockIdx.x * 256 + threadIdx.x;
    float c0 = 0.f, c1 = 0.f, c2 = 0.f, c3 = 0.f;
    if (e < N_EDGES) {
        float4 l = *(float4*)&g_logit[(size_t)e * HEADS];
        c0 = __expf(l.x - g_max[0]);
        c1 = __expf(l.y - g_max[1]);
        c2 = __expf(l.z - g_max[2]);
        c3 = __expf(l.w - g_max[3]);
        *(float4*)&g_logit[(size_t)e * HEADS] = make_float4(c0, c1, c2, c3);
    }
#pragma unroll
    for (int m = 16; m > 0; m >>= 1) {
        c0 += __shfl_xor_sync(0xffffffffu, c0, m);
        c1 += __shfl_xor_sync(0xffffffffu, c1, m);
        c2 += __shfl_xor_sync(0xffffffffu, c2, m);
        c3 += __shfl_xor_sync(0xffffffffu, c3, m);
    }
    if ((threadIdx.x & 31) == 0) {
        atomicAdd(&ssum[0], c0);
        atomicAdd(&ssum[1], c1);
        atomicAdd(&ssum[2], c2);
        atomicAdd(&ssum[3], c3);
    }
    __syncthreads();
    if (threadIdx.x < HEADS) atomicAdd(&g_sum[threadIdx.x], ssum[threadIdx.x]);
}

// ---------------- 5: CSR aggregation (warp per node, no atomics) ------------
__global__ void __launch_bounds__(256) agg_csr_kernel() {
    int wid = threadIdx.x >> 5;
    int lane = threadIdx.x & 31;
    int n = blockIdx.x * 8 + wid;
    if (n >= N_PAD) return;

    int off0 = g_off[n];
    int off1 = g_off[n + 1];
    int h = lane >> 3;

    float4 a0 = make_float4(0.f, 0.f, 0.f, 0.f);
    float4 a1 = make_float4(0.f, 0.f, 0.f, 0.f);

    for (int i = off0; i < off1; i++) {
        int s = g_csr_src[i];
        float c = g_csr_attn[(size_t)i * HEADS + h];
        const float4* v = (const float4*)(g_V + (size_t)s * QKVC) + lane * 2;
        float4 v0 = v[0], v1 = v[1];
        a0.x += c * v0.x; a0.y += c * v0.y; a0.z += c * v0.z; a0.w += c * v0.w;
        a1.x += c * v1.x; a1.y += c * v1.y; a1.z += c * v1.z; a1.w += c * v1.w;
    }

    float4* dst = (float4*)(g_agg + (size_t)n * QKVC) + lane * 2;
    dst[0] = a0;
    dst[1] = a1;
}

// ---------------- 6: output GEMM (+bias), 64x64x16 -------------------------
__global__ void __launch_bounds__(256) out_gemm_kernel(
    const float* __restrict__ B, const float* __restrict__ bias,
    float* __restrict__ C)
{
    const int BM = 64, BK = 16;
    const int M = N_NODES, K = QKVC, NB = OUTC;
    __shared__ float As[BM][BK + 1];
    __shared__ float Bs[BK][68];

    int tid = threadIdx.x;
    int row0 = blockIdx.x * BM;
    int tx = tid & 15, ty = tid >> 4;

    float acc[4][4];
#pragma unroll
    for (int i = 0; i < 4; i++)
#pragma unroll
        for (int j = 0; j < 4; j++) acc[i][j] = 0.f;

    for (int k0 = 0; k0 < K; k0 += BK) {
        {
            int r = tid >> 2;
            int c4 = (tid & 3) * 4;
            int gr = row0 + r;
            float4 v = make_float4(0.f, 0.f, 0.f, 0.f);
            if (gr < M) v = *(const float4*)&g_agg[(size_t)gr * K + k0 + c4];
            As[r][c4 + 0] = v.x; As[r][c4 + 1] = v.y;
            As[r][c4 + 2] = v.z; As[r][c4 + 3] = v.w;
        }
        {
            int r = tid >> 4;
            int c4 = (tid & 15) * 4;
            float4 v = *(const float4*)&B[(size_t)(k0 + r) * NB + c4];
            Bs[r][c4 + 0] = v.x; Bs[r][c4 + 1] = v.y;
            Bs[r][c4 + 2] = v.z; Bs[r][c4 + 3] = v.w;
        }
        __syncthreads();
#pragma unroll
        for (int k = 0; k < BK; k++) {
            float ar[4], br[4];
#pragma unroll
            for (int i = 0; i < 4; i++) ar[i] = As[ty * 4 + i][k];
#pragma unroll
            for (int j = 0; j < 4; j++) br[j] = Bs[k][tx * 4 + j];
#pragma unroll
            for (int i = 0; i < 4; i++)
#pragma unroll
                for (int j = 0; j < 4; j++) acc[i][j] += ar[i] * br[j];
        }
        __syncthreads();
    }

#pragma unroll
    for (int i = 0; i < 4; i++) {
        int r = row0 + ty * 4 + i;
        if (r >= M) continue;
#pragma unroll
        for (int j = 0; j < 4; j++) {
            int c = tx * 4 + j;
            C[(size_t)r * NB + c] = acc[i][j] + bias[c];
        }
    }
}

// ---------------- launch ----------------------------------------------------
extern "C" void kernel_launch(void* const* d_in, const int* in_sizes, int n_in,
                              void* d_out, int out_size) {
    const float* x    = (const float*)d_in[0];
    const void*  ei   = d_in[1];
    const float* ew   = (const float*)d_in[2];
    const float* Wq   = (const float*)d_in[3];
    const float* Wk   = (const float*)d_in[4];
    const float* Wv   = (const float*)d_in[5];
    const float* We   = (const float*)d_in[6];
    const float* Wout = (const float*)d_in[7];
    const float* bout = (const float*)d_in[8];
    float* out = (float*)d_out;

    static bool attr_set = false;
    if (!attr_set) {
        cudaFuncSetAttribute(qkv_wmma_kernel,
                             cudaFuncAttributeMaxDynamicSharedMemorySize, SM_QKV);
        attr_set = true;
    }

    detect_idx_kernel<<<1, 32>>>((const int*)ei);
    zero_small_kernel<<<(N_PAD + 255) / 256, 256>>>();

    prep_x_kernel<<<(N_PAD * 16 + 255) / 256, 256>>>(x);
    prep_w_kernel<<<48, 256>>>(Wq, Wk, Wv);

    dim3 qgrid(M_TILES, 2);
    qkv_wmma_kernel<<<qgrid, 256, SM_QKV>>>();

    // CSR build (independent of Q/K/V; overlaps pipeline-wise on same stream)
    hist_kernel<<<(N_EDGES + 255) / 256, 256>>>(ei);
    scan_kernel<<<1, 1024>>>();

    edge_logits_kernel<<<LOGIT_BLOCKS, 256>>>(ei, ew, We);
    reduce_max_kernel<<<HEADS, 256>>>();
    coef_kernel<<<(N_EDGES + 255) / 256, 256>>>();

    scatter_kernel<<<(N_EDGES + 255) / 256, 256>>>(ei);
    agg_csr_kernel<<<(N_PAD + 7) / 8, 256>>>();

    out_gemm_kernel<<<N_PAD / 64, 256>>>(Wout, bout, out);
}

// round 9
// speedup vs baseline: 1.5449x; 1.5449x over previous
#include <cuda_runtime.h>
#include <cuda_bf16.h>
#include <mma.h>
#include <cstdint>

using namespace nvcuda;

#define N_NODES 50000
#define N_EDGES 500000
#define IN_CH   128
#define QKVC    256        // OUT_CH * HEADS
#define OUTC    64
#define HEADS   4
#define N_PAD   50048      // 391*128 = 782*64
#define M_TILES (N_PAD / 128)        // 391
#define NODE_BLOCKS ((N_PAD + 7) / 8)   // 6256 (warp per node, 8 warps/block)

// ---------------- scratch (device globals; no allocation allowed) ----------
__device__ float g_Q[(size_t)N_PAD * QKVC];
__device__ float g_K[(size_t)N_PAD * QKVC];
__device__ float g_V[(size_t)N_PAD * QKVC];
__device__ float g_agg[(size_t)N_PAD * QKVC];
__device__ __align__(16) float g_logit[(size_t)N_EDGES * HEADS];  // CSR-ordered; logits then exp
__device__ float g_blockmax[NODE_BLOCKS * HEADS];
__device__ float g_max[HEADS];
__device__ float g_sum[HEADS];
__device__ int   g_idx64;

// CSR-by-target structures
__device__ int    g_deg[N_PAD];
__device__ int    g_pos[N_PAD];
__device__ int    g_off[N_PAD + 1];
__device__ int    g_csr_src[N_EDGES];
__device__ float  g_csr_ew[N_EDGES];

// split-bf16 operands for the HMMA path
__device__ __align__(16) uint4 g_xhi[(size_t)N_PAD * 16];   // [N_PAD][128] bf16 rows, 8 per uint4
__device__ __align__(16) uint4 g_xlo[(size_t)N_PAD * 16];
__device__ __align__(16) uint4 g_Wt[3 * 2 * 256 * 16];      // [w][hi/lo][n=256][k=128] bf16 (W^T)

// ---------------- helpers --------------------------------------------------
__device__ __forceinline__ void load_edge(const void* ei_raw, int e, int idx64,
                                          int& s, int& t) {
    if (idx64) {
        const long long* p = (const long long*)ei_raw;
        s = (int)p[e];
        t = (int)p[N_EDGES + e];
    } else {
        const int* p = (const int*)ei_raw;
        s = p[e];
        t = p[N_EDGES + e];
    }
}
__device__ __forceinline__ int load_tgt(const void* ei_raw, int e, int idx64) {
    if (idx64) return (int)((const long long*)ei_raw)[N_EDGES + e];
    return ((const int*)ei_raw)[N_EDGES + e];
}

// ---------------- 0: dtype sniff + zero small scratch ----------------------
__global__ void detect_idx_kernel(const int* ei32) {
    if (blockIdx.x == 0 && threadIdx.x == 0) {
        int zeros = 0;
        for (int i = 0; i < 64; i++)
            if (ei32[2 * i + 1] == 0) zeros++;
        g_idx64 = (zeros >= 60) ? 1 : 0;
    }
}
__global__ void zero_small_kernel() {
    int i = blockIdx.x * 256 + threadIdx.x;
    if (i < N_PAD) { g_deg[i] = 0; g_pos[i] = 0; }
    if (i < HEADS) g_sum[i] = 0.f;
}

// ---------------- 1a: split x -> bf16 hi/lo ---------------------------------
__global__ void __launch_bounds__(256) prep_x_kernel(const float* __restrict__ x) {
    int t = blockIdx.x * 256 + threadIdx.x;       // one per 8-float chunk
    if (t >= N_PAD * 16) return;
    int r = t >> 4, c8 = t & 15;
    float v[8];
    if (r < N_NODES) {
        float4 a = *(const float4*)&x[(size_t)r * IN_CH + c8 * 8];
        float4 b = *(const float4*)&x[(size_t)r * IN_CH + c8 * 8 + 4];
        v[0] = a.x; v[1] = a.y; v[2] = a.z; v[3] = a.w;
        v[4] = b.x; v[5] = b.y; v[6] = b.z; v[7] = b.w;
    } else {
#pragma unroll
        for (int j = 0; j < 8; j++) v[j] = 0.f;
    }
    union { __nv_bfloat16 h[8]; uint4 u; } hi, lo;
#pragma unroll
    for (int j = 0; j < 8; j++) {
        __nv_bfloat16 h = __float2bfloat16_rn(v[j]);
        hi.h[j] = h;
        lo.h[j] = __float2bfloat16_rn(v[j] - __bfloat162float(h));
    }
    g_xhi[t] = hi.u;
    g_xlo[t] = lo.u;
}

// ---------------- 1b: W^T hi/lo images ([n][k] row-major bf16) --------------
__global__ void __launch_bounds__(256) prep_w_kernel(
    const float* __restrict__ Wq, const float* __restrict__ Wk,
    const float* __restrict__ Wv) {
    int t = blockIdx.x * 256 + threadIdx.x;       // 3*256*16 = 12288 (w, n, k8)
    if (t >= 3 * 256 * 16) return;
    int w = t >> 12;
    int n = (t >> 4) & 255;
    int k8 = t & 15;
    const float* W = (w == 0) ? Wq : (w == 1) ? Wk : Wv;
    union { __nv_bfloat16 h[8]; uint4 u; } hi, lo;
#pragma unroll
    for (int j = 0; j < 8; j++) {
        float v = W[(size_t)(k8 * 8 + j) * QKVC + n];
        __nv_bfloat16 h = __float2bfloat16_rn(v);
        hi.h[j] = h;
        lo.h[j] = __float2bfloat16_rn(v - __bfloat162float(h));
    }
    g_Wt[((w * 2 + 0) * 256 + n) * 16 + k8] = hi.u;
    g_Wt[((w * 2 + 1) * 256 + n) * 16 + k8] = lo.u;
}

// ---------------- 1c: QKV GEMM via wmma bf16 (fused 3-term split) ----------
// grid (391, 2): A hi/lo + B hi/lo staged in SMEM (139KB), z-loop refills B.
#define LDA 136                                    // padded ld (elements)
static constexpr int SA_HI = 0;
static constexpr int SA_LO = 128 * LDA * 2;        // 34816
static constexpr int SB_HI = SA_LO + 128 * LDA * 2;
static constexpr int SB_LO = SB_HI + 128 * LDA * 2;
static constexpr int SM_QKV = SB_LO + 128 * LDA * 2;  // 139264 bytes

__global__ void __launch_bounds__(256) qkv_wmma_kernel() {
    extern __shared__ __align__(16) char smem[];
    __nv_bfloat16* Ahi = (__nv_bfloat16*)(smem + SA_HI);
    __nv_bfloat16* Alo = (__nv_bfloat16*)(smem + SA_LO);
    __nv_bfloat16* Bhi = (__nv_bfloat16*)(smem + SB_HI);
    __nv_bfloat16* Blo = (__nv_bfloat16*)(smem + SB_LO);

    int tid = threadIdx.x;
    int bx = blockIdx.x, by = blockIdx.y;
    int wid = tid >> 5;
    int wr = wid & 3;           // warp row (4 x 32 rows)
    int wc = wid >> 2;          // warp col (2 x 64 cols)

    // stage A hi/lo (128 rows x 128 k)
    for (int i = tid; i < 2048; i += 256) {
        int r = i >> 4, c8 = i & 15;
        size_t src = (size_t)(bx * 128 + r) * 16 + c8;
        *(uint4*)&Ahi[r * LDA + c8 * 8] = g_xhi[src];
        *(uint4*)&Alo[r * LDA + c8 * 8] = g_xlo[src];
    }

    for (int z = 0; z < 3; z++) {
        // stage B hi/lo for this weight
        for (int i = tid; i < 2048; i += 256) {
            int nl = i >> 4, k8 = i & 15;
            int n = by * 128 + nl;
            *(uint4*)&Bhi[nl * LDA + k8 * 8] = g_Wt[((z * 2 + 0) * 256 + n) * 16 + k8];
            *(uint4*)&Blo[nl * LDA + k8 * 8] = g_Wt[((z * 2 + 1) * 256 + n) * 16 + k8];
        }
        __syncthreads();

        wmma::fragment<wmma::accumulator, 16, 16, 16, float> acc[2][4];
#pragma unroll
        for (int i = 0; i < 2; i++)
#pragma unroll
            for (int j = 0; j < 4; j++) wmma::fill_fragment(acc[i][j], 0.f);

#pragma unroll
        for (int k0 = 0; k0 < 128; k0 += 16) {
            wmma::fragment<wmma::matrix_a, 16, 16, 16, __nv_bfloat16, wmma::row_major> ah[2], al[2];
            wmma::load_matrix_sync(ah[0], Ahi + (wr * 32 + 0)  * LDA + k0, LDA);
            wmma::load_matrix_sync(ah[1], Ahi + (wr * 32 + 16) * LDA + k0, LDA);
            wmma::load_matrix_sync(al[0], Alo + (wr * 32 + 0)  * LDA + k0, LDA);
            wmma::load_matrix_sync(al[1], Alo + (wr * 32 + 16) * LDA + k0, LDA);
#pragma unroll
            for (int j = 0; j < 4; j++) {
                wmma::fragment<wmma::matrix_b, 16, 16, 16, __nv_bfloat16, wmma::col_major> bh, bl;
                wmma::load_matrix_sync(bh, Bhi + (wc * 64 + j * 16) * LDA + k0, LDA);
                wmma::load_matrix_sync(bl, Blo + (wc * 64 + j * 16) * LDA + k0, LDA);
                wmma::mma_sync(acc[0][j], ah[0], bh, acc[0][j]);
                wmma::mma_sync(acc[1][j], ah[1], bh, acc[1][j]);
                wmma::mma_sync(acc[0][j], ah[0], bl, acc[0][j]);
                wmma::mma_sync(acc[1][j], ah[1], bl, acc[1][j]);
                wmma::mma_sync(acc[0][j], al[0], bh, acc[0][j]);
                wmma::mma_sync(acc[1][j], al[1], bh, acc[1][j]);
            }
        }

        float* C = (z == 0) ? g_Q : (z == 1) ? g_K : g_V;
        int row0 = bx * 128 + wr * 32;
        int col0 = by * 128 + wc * 64;
#pragma unroll
        for (int i = 0; i < 2; i++)
#pragma unroll
            for (int j = 0; j < 4; j++)
                wmma::store_matrix_sync(&C[(size_t)(row0 + i * 16) * QKVC + col0 + j * 16],
                                        acc[i][j], QKVC, wmma::mem_row_major);
        __syncthreads();   // protect B tiles before next z overwrites them
    }
}

// ---------------- CSR build: histogram -> scan -> scatter -------------------
__global__ void __launch_bounds__(256) hist_kernel(const void* __restrict__ ei_raw) {
    int e = blockIdx.x * 256 + threadIdx.x;
    if (e >= N_EDGES) return;
    int t = load_tgt(ei_raw, e, g_idx64);
    atomicAdd(&g_deg[t], 1);
}

__global__ void __launch_bounds__(1024) scan_kernel() {
    const int CH = (N_PAD + 1023) / 1024;   // 49
    __shared__ int ssum[1024];
    int t = threadIdx.x;
    int base = t * CH;
    int s = 0;
    for (int i = 0; i < CH; i++) {
        int idx = base + i;
        if (idx < N_PAD) s += g_deg[idx];
    }
    ssum[t] = s;
    __syncthreads();
    for (int off = 1; off < 1024; off <<= 1) {
        int v = 0;
        if (t >= off) v = ssum[t - off];
        __syncthreads();
        ssum[t] += v;
        __syncthreads();
    }
    int run = ssum[t] - s;                  // exclusive base for this chunk
    for (int i = 0; i < CH; i++) {
        int idx = base + i;
        if (idx < N_PAD) { g_off[idx] = run; run += g_deg[idx]; }
    }
    if (t == 1023) g_off[N_PAD] = run;
}

__global__ void __launch_bounds__(256) scatter_kernel(
    const void* __restrict__ ei_raw, const float* __restrict__ ew) {
    int e = blockIdx.x * 256 + threadIdx.x;
    if (e >= N_EDGES) return;
    int s, t;
    load_edge(ei_raw, e, g_idx64, s, t);
    int slot = g_off[t] + atomicAdd(&g_pos[t], 1);
    g_csr_src[slot] = s;
    g_csr_ew[slot] = ew[e];
}

// ---------------- 2: logits in CSR order (warp per target node) -------------
// Q[t] row loaded once into registers, reused across the node's edges.
__global__ void __launch_bounds__(256) edge_logits_csr_kernel(
    const float* __restrict__ We)
{
    __shared__ float wvals[8][HEADS];
    int wid = threadIdx.x >> 5;
    int lane = threadIdx.x & 31;
    int n = blockIdx.x * 8 + wid;

    float m = -3.4e38f;
    int h = lane >> 3;

    if (n < N_PAD) {
        int off0 = g_off[n];
        int off1 = g_off[n + 1];
        if (off0 < off1) {
            const float4* q = (const float4*)(g_Q + (size_t)n * QKVC);
            float4 q0 = q[lane * 2], q1 = q[lane * 2 + 1];
            float we = We[h];

            for (int i = off0; i < off1; i++) {
                int s = g_csr_src[i];
                const float4* k = (const float4*)(g_K + (size_t)s * QKVC);
                float4 k0 = k[lane * 2], k1 = k[lane * 2 + 1];
                float ps = q0.x * k0.x + q0.y * k0.y + q0.z * k0.z + q0.w * k0.w
                         + q1.x * k1.x + q1.y * k1.y + q1.z * k1.z + q1.w * k1.w;
                ps += __shfl_xor_sync(0xffffffffu, ps, 4);
                ps += __shfl_xor_sync(0xffffffffu, ps, 2);
                ps += __shfl_xor_sync(0xffffffffu, ps, 1);
                if ((lane & 7) == 0) {
                    float logit = ps * 0.125f + g_csr_ew[i] * we;   // 1/sqrt(64)
                    logit = (logit > 0.f) ? logit : 0.2f * logit;
                    g_logit[(size_t)i * HEADS + h] = logit;
                    m = fmaxf(m, logit);
                }
            }
        }
    }
    // per-block max (heads tracked by lanes 0,8,16,24 of each warp)
    if ((lane & 7) == 0) wvals[wid][h] = m;
    __syncthreads();
    if (threadIdx.x < HEADS) {
        float bm = wvals[0][threadIdx.x];
#pragma unroll
        for (int w = 1; w < 8; w++) bm = fmaxf(bm, wvals[w][threadIdx.x]);
        g_blockmax[blockIdx.x * HEADS + threadIdx.x] = bm;
    }
}

// ---------------- 3: global max per head -----------------------------------
__global__ void reduce_max_kernel() {
    int h = blockIdx.x;
    __shared__ float sm[256];
    float m = -3.4e38f;
    for (int i = threadIdx.x; i < NODE_BLOCKS; i += 256)
        m = fmaxf(m, g_blockmax[i * HEADS + h]);
    sm[threadIdx.x] = m;
    __syncthreads();
    for (int s = 128; s > 0; s >>= 1) {
        if (threadIdx.x < s) sm[threadIdx.x] = fmaxf(sm[threadIdx.x], sm[threadIdx.x + s]);
        __syncthreads();
    }
    if (threadIdx.x == 0) g_max[h] = sm[0];
}

// ---------------- 4: exp (in place) + per-head sum -------------------------
__global__ void __launch_bounds__(256) coef_kernel() {
    __shared__ float ssum[HEADS];
    if (threadIdx.x < HEADS) ssum[threadIdx.x] = 0.f;
    __syncthreads();

    int e = blockIdx.x * 256 + threadIdx.x;
    float c0 = 0.f, c1 = 0.f, c2 = 0.f, c3 = 0.f;
    if (e < N_EDGES) {
        float4 l = *(float4*)&g_logit[(size_t)e * HEADS];
        c0 = __expf(l.x - g_max[0]);
        c1 = __expf(l.y - g_max[1]);
        c2 = __expf(l.z - g_max[2]);
        c3 = __expf(l.w - g_max[3]);
        *(float4*)&g_logit[(size_t)e * HEADS] = make_float4(c0, c1, c2, c3);
    }
#pragma unroll
    for (int m = 16; m > 0; m >>= 1) {
        c0 += __shfl_xor_sync(0xffffffffu, c0, m);
        c1 += __shfl_xor_sync(0xffffffffu, c1, m);
        c2 += __shfl_xor_sync(0xffffffffu, c2, m);
        c3 += __shfl_xor_sync(0xffffffffu, c3, m);
    }
    if ((threadIdx.x & 31) == 0) {
        atomicAdd(&ssum[0], c0);
        atomicAdd(&ssum[1], c1);
        atomicAdd(&ssum[2], c2);
        atomicAdd(&ssum[3], c3);
    }
    __syncthreads();
    if (threadIdx.x < HEADS) atomicAdd(&g_sum[threadIdx.x], ssum[threadIdx.x]);
}

// ---------------- 5: CSR aggregation (warp per node, no atomics) ------------
// out_row(n) = (1/sum_h) * sum_i exp_i * V[src_i]   (normalization hoisted)
__global__ void __launch_bounds__(256) agg_csr_kernel() {
    int wid = threadIdx.x >> 5;
    int lane = threadIdx.x & 31;
    int n = blockIdx.x * 8 + wid;
    if (n >= N_PAD) return;

    int off0 = g_off[n];
    int off1 = g_off[n + 1];
    int h = lane >> 3;

    float4 a0 = make_float4(0.f, 0.f, 0.f, 0.f);
    float4 a1 = make_float4(0.f, 0.f, 0.f, 0.f);

    for (int i = off0; i < off1; i++) {
        int s = g_csr_src[i];
        float c = g_logit[(size_t)i * HEADS + h];
        const float4* v = (const float4*)(g_V + (size_t)s * QKVC) + lane * 2;
        float4 v0 = v[0], v1 = v[1];
        a0.x += c * v0.x; a0.y += c * v0.y; a0.z += c * v0.z; a0.w += c * v0.w;
        a1.x += c * v1.x; a1.y += c * v1.y; a1.z += c * v1.z; a1.w += c * v1.w;
    }

    float inv = 1.0f / g_sum[h];
    a0.x *= inv; a0.y *= inv; a0.z *= inv; a0.w *= inv;
    a1.x *= inv; a1.y *= inv; a1.z *= inv; a1.w *= inv;

    float4* dst = (float4*)(g_agg + (size_t)n * QKVC) + lane * 2;
    dst[0] = a0;
    dst[1] = a1;
}

// ---------------- 6: output GEMM (+bias), 64x64x16 -------------------------
__global__ void __launch_bounds__(256) out_gemm_kernel(
    const float* __restrict__ B, const float* __restrict__ bias,
    float* __restrict__ C)
{
    const int BM = 64, BK = 16;
    const int M = N_NODES, K = QKVC, NB = OUTC;
    __shared__ float As[BM][BK + 1];
    __shared__ float Bs[BK][68];

    int tid = threadIdx.x;
    int row0 = blockIdx.x * BM;
    int tx = tid & 15, ty = tid >> 4;

    float acc[4][4];
#pragma unroll
    for (int i = 0; i < 4; i++)
#pragma unroll
        for (int j = 0; j < 4; j++) acc[i][j] = 0.f;

    for (int k0 = 0; k0 < K; k0 += BK) {
        {
            int r = tid >> 2;
            int c4 = (tid & 3) * 4;
            int gr = row0 + r;
            float4 v = make_float4(0.f, 0.f, 0.f, 0.f);
            if (gr < M) v = *(const float4*)&g_agg[(size_t)gr * K + k0 + c4];
            As[r][c4 + 0] = v.x; As[r][c4 + 1] = v.y;
            As[r][c4 + 2] = v.z; As[r][c4 + 3] = v.w;
        }
        {
            int r = tid >> 4;
            int c4 = (tid & 15) * 4;
            float4 v = *(const float4*)&B[(size_t)(k0 + r) * NB + c4];
            Bs[r][c4 + 0] = v.x; Bs[r][c4 + 1] = v.y;
            Bs[r][c4 + 2] = v.z; Bs[r][c4 + 3] = v.w;
        }
        __syncthreads();
#pragma unroll
        for (int k = 0; k < BK; k++) {
            float ar[4], br[4];
#pragma unroll
            for (int i = 0; i < 4; i++) ar[i] = As[ty * 4 + i][k];
#pragma unroll
            for (int j = 0; j < 4; j++) br[j] = Bs[k][tx * 4 + j];
#pragma unroll
            for (int i = 0; i < 4; i++)
#pragma unroll
                for (int j = 0; j < 4; j++) acc[i][j] += ar[i] * br[j];
        }
        __syncthreads();
    }

#pragma unroll
    for (int i = 0; i < 4; i++) {
        int r = row0 + ty * 4 + i;
        if (r >= M) continue;
#pragma unroll
        for (int j = 0; j < 4; j++) {
            int c = tx * 4 + j;
            C[(size_t)r * NB + c] = acc[i][j] + bias[c];
        }
    }
}

// ---------------- launch ----------------------------------------------------
extern "C" void kernel_launch(void* const* d_in, const int* in_sizes, int n_in,
                              void* d_out, int out_size) {
    const float* x    = (const float*)d_in[0];
    const void*  ei   = d_in[1];
    const float* ew   = (const float*)d_in[2];
    const float* Wq   = (const float*)d_in[3];
    const float* Wk   = (const float*)d_in[4];
    const float* Wv   = (const float*)d_in[5];
    const float* We   = (const float*)d_in[6];
    const float* Wout = (const float*)d_in[7];
    const float* bout = (const float*)d_in[8];
    float* out = (float*)d_out;

    static bool attr_set = false;
    if (!attr_set) {
        cudaFuncSetAttribute(qkv_wmma_kernel,
                             cudaFuncAttributeMaxDynamicSharedMemorySize, SM_QKV);
        attr_set = true;
    }

    detect_idx_kernel<<<1, 32>>>((const int*)ei);
    zero_small_kernel<<<(N_PAD + 255) / 256, 256>>>();

    prep_x_kernel<<<(N_PAD * 16 + 255) / 256, 256>>>(x);
    prep_w_kernel<<<48, 256>>>(Wq, Wk, Wv);

    // CSR build (only needs edge_index + ew)
    hist_kernel<<<(N_EDGES + 255) / 256, 256>>>(ei);
    scan_kernel<<<1, 1024>>>();
    scatter_kernel<<<(N_EDGES + 255) / 256, 256>>>(ei, ew);

    // Q,K,V = x @ W*  (wmma bf16 split)
    dim3 qgrid(M_TILES, 2);
    qkv_wmma_kernel<<<qgrid, 256, SM_QKV>>>();

    // edge phase, all in CSR order
    edge_logits_csr_kernel<<<NODE_BLOCKS, 256>>>(We);
    reduce_max_kernel<<<HEADS, 256>>>();
    coef_kernel<<<(N_EDGES + 255) / 256, 256>>>();
    agg_csr_kernel<<<NODE_BLOCKS, 256>>>();

    out_gemm_kernel<<<N_PAD / 64, 256>>>(Wout, bout, out);
}

// round 11
// speedup vs baseline: 1.8350x; 1.1878x over previous
#include <cuda_runtime.h>
#include <cuda_bf16.h>
#include <mma.h>
#include <cstdint>

using namespace nvcuda;

#define N_NODES 50000
#define N_EDGES 500000
#define IN_CH   128
#define QKVC    256        // OUT_CH * HEADS
#define OUTC    64
#define HEADS   4
#define N_PAD   50048      // 391*128 = 782*64
#define M_TILES (N_PAD / 128)        // 391
#define NODE_BLOCKS ((N_PAD + 7) / 8)   // 6256 (warp per node, 8 warps/block)

// ---------------- scratch (device globals; no allocation allowed) ----------
__device__ float g_Q[(size_t)N_PAD * QKVC];
__device__ float g_K[(size_t)N_PAD * QKVC];
__device__ float g_V[(size_t)N_PAD * QKVC];
__device__ float g_agg[(size_t)N_PAD * QKVC];
__device__ __align__(16) float g_logit[(size_t)N_EDGES * HEADS];  // CSR-ordered; logits then exp
__device__ float g_blockmax[NODE_BLOCKS * HEADS];
__device__ float g_max[HEADS];
__device__ float g_sum[HEADS];
__device__ int   g_idx64;

// CSR-by-target structures
__device__ int    g_deg[N_PAD];
__device__ int    g_pos[N_PAD];
__device__ int    g_off[N_PAD + 1];
__device__ int    g_csr_src[N_EDGES];
__device__ float  g_csr_ew[N_EDGES];

// split-bf16 operands for the HMMA path
__device__ __align__(16) uint4 g_xhi[(size_t)N_PAD * 16];   // [N_PAD][128] bf16 rows, 8 per uint4
__device__ __align__(16) uint4 g_xlo[(size_t)N_PAD * 16];
__device__ __align__(16) uint4 g_Wt[3 * 2 * 256 * 16];      // [w][hi/lo][n=256][k=128] bf16 (W^T)

// ---------------- helpers --------------------------------------------------
__device__ __forceinline__ void load_edge(const void* ei_raw, int e, int idx64,
                                          int& s, int& t) {
    if (idx64) {
        const long long* p = (const long long*)ei_raw;
        s = (int)p[e];
        t = (int)p[N_EDGES + e];
    } else {
        const int* p = (const int*)ei_raw;
        s = p[e];
        t = p[N_EDGES + e];
    }
}
__device__ __forceinline__ int load_tgt(const void* ei_raw, int e, int idx64) {
    if (idx64) return (int)((const long long*)ei_raw)[N_EDGES + e];
    return ((const int*)ei_raw)[N_EDGES + e];
}

// ---------------- 0: dtype sniff + zero small scratch ----------------------
__global__ void detect_idx_kernel(const int* ei32) {
    if (blockIdx.x == 0 && threadIdx.x == 0) {
        int zeros = 0;
        for (int i = 0; i < 64; i++)
            if (ei32[2 * i + 1] == 0) zeros++;
        g_idx64 = (zeros >= 60) ? 1 : 0;
    }
}
__global__ void zero_small_kernel() {
    int i = blockIdx.x * 256 + threadIdx.x;
    if (i < N_PAD) { g_deg[i] = 0; g_pos[i] = 0; }
    if (i < HEADS) g_sum[i] = 0.f;
}

// ---------------- 1a: split x -> bf16 hi/lo ---------------------------------
__global__ void __launch_bounds__(256) prep_x_kernel(const float* __restrict__ x) {
    int t = blockIdx.x * 256 + threadIdx.x;       // one per 8-float chunk
    if (t >= N_PAD * 16) return;
    int r = t >> 4, c8 = t & 15;
    float v[8];
    if (r < N_NODES) {
        float4 a = *(const float4*)&x[(size_t)r * IN_CH + c8 * 8];
        float4 b = *(const float4*)&x[(size_t)r * IN_CH + c8 * 8 + 4];
        v[0] = a.x; v[1] = a.y; v[2] = a.z; v[3] = a.w;
        v[4] = b.x; v[5] = b.y; v[6] = b.z; v[7] = b.w;
    } else {
#pragma unroll
        for (int j = 0; j < 8; j++) v[j] = 0.f;
    }
    union { __nv_bfloat16 h[8]; uint4 u; } hi, lo;
#pragma unroll
    for (int j = 0; j < 8; j++) {
        __nv_bfloat16 h = __float2bfloat16_rn(v[j]);
        hi.h[j] = h;
        lo.h[j] = __float2bfloat16_rn(v[j] - __bfloat162float(h));
    }
    g_xhi[t] = hi.u;
    g_xlo[t] = lo.u;
}

// ---------------- 1b: W^T hi/lo images ([n][k] row-major bf16) --------------
__global__ void __launch_bounds__(256) prep_w_kernel(
    const float* __restrict__ Wq, const float* __restrict__ Wk,
    const float* __restrict__ Wv) {
    int t = blockIdx.x * 256 + threadIdx.x;       // 3*256*16 = 12288 (w, n, k8)
    if (t >= 3 * 256 * 16) return;
    int w = t >> 12;
    int n = (t >> 4) & 255;
    int k8 = t & 15;
    const float* W = (w == 0) ? Wq : (w == 1) ? Wk : Wv;
    union { __nv_bfloat16 h[8]; uint4 u; } hi, lo;
#pragma unroll
    for (int j = 0; j < 8; j++) {
        float v = W[(size_t)(k8 * 8 + j) * QKVC + n];
        __nv_bfloat16 h = __float2bfloat16_rn(v);
        hi.h[j] = h;
        lo.h[j] = __float2bfloat16_rn(v - __bfloat162float(h));
    }
    g_Wt[((w * 2 + 0) * 256 + n) * 16 + k8] = hi.u;
    g_Wt[((w * 2 + 1) * 256 + n) * 16 + k8] = lo.u;
}

// ---------------- 1c: QKV GEMM via wmma bf16 (fused 3-term split) ----------
// grid (391, 2, nz): z = zbase + blockIdx.z selects the weight (0=Q,1=K,2=V).
#define LDA 136                                    // padded ld (elements)
static constexpr int SA_HI = 0;
static constexpr int SA_LO = 128 * LDA * 2;        // 34816
static constexpr int SB_HI = SA_LO + 128 * LDA * 2;
static constexpr int SB_LO = SB_HI + 128 * LDA * 2;
static constexpr int SM_QKV = SB_LO + 128 * LDA * 2;  // 139264 bytes

__global__ void __launch_bounds__(256) qkv_wmma_kernel(int zbase) {
    extern __shared__ __align__(16) char smem[];
    __nv_bfloat16* Ahi = (__nv_bfloat16*)(smem + SA_HI);
    __nv_bfloat16* Alo = (__nv_bfloat16*)(smem + SA_LO);
    __nv_bfloat16* Bhi = (__nv_bfloat16*)(smem + SB_HI);
    __nv_bfloat16* Blo = (__nv_bfloat16*)(smem + SB_LO);

    int tid = threadIdx.x;
    int bx = blockIdx.x, by = blockIdx.y;
    int z = zbase + blockIdx.z;
    int wid = tid >> 5;
    int wr = wid & 3;           // warp row (4 x 32 rows)
    int wc = wid >> 2;          // warp col (2 x 64 cols)

    // stage A hi/lo (128 rows x 128 k) and B hi/lo for this weight
    for (int i = tid; i < 2048; i += 256) {
        int r = i >> 4, c8 = i & 15;
        size_t src = (size_t)(bx * 128 + r) * 16 + c8;
        *(uint4*)&Ahi[r * LDA + c8 * 8] = g_xhi[src];
        *(uint4*)&Alo[r * LDA + c8 * 8] = g_xlo[src];
        int n = by * 128 + r;
        *(uint4*)&Bhi[r * LDA + c8 * 8] = g_Wt[((z * 2 + 0) * 256 + n) * 16 + c8];
        *(uint4*)&Blo[r * LDA + c8 * 8] = g_Wt[((z * 2 + 1) * 256 + n) * 16 + c8];
    }
    __syncthreads();

    wmma::fragment<wmma::accumulator, 16, 16, 16, float> acc[2][4];
#pragma unroll
    for (int i = 0; i < 2; i++)
#pragma unroll
        for (int j = 0; j < 4; j++) wmma::fill_fragment(acc[i][j], 0.f);

#pragma unroll
    for (int k0 = 0; k0 < 128; k0 += 16) {
        wmma::fragment<wmma::matrix_a, 16, 16, 16, __nv_bfloat16, wmma::row_major> ah[2], al[2];
        wmma::load_matrix_sync(ah[0], Ahi + (wr * 32 + 0)  * LDA + k0, LDA);
        wmma::load_matrix_sync(ah[1], Ahi + (wr * 32 + 16) * LDA + k0, LDA);
        wmma::load_matrix_sync(al[0], Alo + (wr * 32 + 0)  * LDA + k0, LDA);
        wmma::load_matrix_sync(al[1], Alo + (wr * 32 + 16) * LDA + k0, LDA);
#pragma unroll
        for (int j = 0; j < 4; j++) {
            wmma::fragment<wmma::matrix_b, 16, 16, 16, __nv_bfloat16, wmma::col_major> bh, bl;
            wmma::load_matrix_sync(bh, Bhi + (wc * 64 + j * 16) * LDA + k0, LDA);
            wmma::load_matrix_sync(bl, Blo + (wc * 64 + j * 16) * LDA + k0, LDA);
            wmma::mma_sync(acc[0][j], ah[0], bh, acc[0][j]);
            wmma::mma_sync(acc[1][j], ah[1], bh, acc[1][j]);
            wmma::mma_sync(acc[0][j], ah[0], bl, acc[0][j]);
            wmma::mma_sync(acc[1][j], ah[1], bl, acc[1][j]);
            wmma::mma_sync(acc[0][j], al[0], bh, acc[0][j]);
            wmma::mma_sync(acc[1][j], al[1], bh, acc[1][j]);
        }
    }

    float* C = (z == 0) ? g_Q : (z == 1) ? g_K : g_V;
    int row0 = bx * 128 + wr * 32;
    int col0 = by * 128 + wc * 64;
#pragma unroll
    for (int i = 0; i < 2; i++)
#pragma unroll
        for (int j = 0; j < 4; j++)
            wmma::store_matrix_sync(&C[(size_t)(row0 + i * 16) * QKVC + col0 + j * 16],
                                    acc[i][j], QKVC, wmma::mem_row_major);
}

// ---------------- CSR build: histogram -> scan -> scatter -------------------
__global__ void __launch_bounds__(256) hist_kernel(const void* __restrict__ ei_raw) {
    int e = blockIdx.x * 256 + threadIdx.x;
    if (e >= N_EDGES) return;
    int t = load_tgt(ei_raw, e, g_idx64);
    atomicAdd(&g_deg[t], 1);
}

__global__ void __launch_bounds__(1024) scan_kernel() {
    const int CH = (N_PAD + 1023) / 1024;   // 49
    __shared__ int ssum[1024];
    int t = threadIdx.x;
    int base = t * CH;
    int s = 0;
    for (int i = 0; i < CH; i++) {
        int idx = base + i;
        if (idx < N_PAD) s += g_deg[idx];
    }
    ssum[t] = s;
    __syncthreads();
    for (int off = 1; off < 1024; off <<= 1) {
        int v = 0;
        if (t >= off) v = ssum[t - off];
        __syncthreads();
        ssum[t] += v;
        __syncthreads();
    }
    int run = ssum[t] - s;                  // exclusive base for this chunk
    for (int i = 0; i < CH; i++) {
        int idx = base + i;
        if (idx < N_PAD) { g_off[idx] = run; run += g_deg[idx]; }
    }
    if (t == 1023) g_off[N_PAD] = run;
}

__global__ void __launch_bounds__(256) scatter_kernel(
    const void* __restrict__ ei_raw, const float* __restrict__ ew) {
    int e = blockIdx.x * 256 + threadIdx.x;
    if (e >= N_EDGES) return;
    int s, t;
    load_edge(ei_raw, e, g_idx64, s, t);
    int slot = g_off[t] + atomicAdd(&g_pos[t], 1);
    g_csr_src[slot] = s;
    g_csr_ew[slot] = ew[e];
}

// ---------------- 2: logits in CSR order (warp per target node) -------------
__global__ void __launch_bounds__(256) edge_logits_csr_kernel(
    const float* __restrict__ We)
{
    __shared__ float wvals[8][HEADS];
    int wid = threadIdx.x >> 5;
    int lane = threadIdx.x & 31;
    int n = blockIdx.x * 8 + wid;

    float m = -3.4e38f;
    int h = lane >> 3;

    if (n < N_PAD) {
        int off0 = g_off[n];
        int off1 = g_off[n + 1];
        if (off0 < off1) {
            const float4* q = (const float4*)(g_Q + (size_t)n * QKVC);
            float4 q0 = q[lane * 2], q1 = q[lane * 2 + 1];
            float we = We[h];

#pragma unroll 2
            for (int i = off0; i < off1; i++) {
                int s = g_csr_src[i];
                const float4* k = (const float4*)(g_K + (size_t)s * QKVC);
                float4 k0 = k[lane * 2], k1 = k[lane * 2 + 1];
                float ps = q0.x * k0.x + q0.y * k0.y + q0.z * k0.z + q0.w * k0.w
                         + q1.x * k1.x + q1.y * k1.y + q1.z * k1.z + q1.w * k1.w;
                ps += __shfl_xor_sync(0xffffffffu, ps, 4);
                ps += __shfl_xor_sync(0xffffffffu, ps, 2);
                ps += __shfl_xor_sync(0xffffffffu, ps, 1);
                if ((lane & 7) == 0) {
                    float logit = ps * 0.125f + g_csr_ew[i] * we;   // 1/sqrt(64)
                    logit = (logit > 0.f) ? logit : 0.2f * logit;
                    g_logit[(size_t)i * HEADS + h] = logit;
                    m = fmaxf(m, logit);
                }
            }
        }
    }
    if ((lane & 7) == 0) wvals[wid][h] = m;
    __syncthreads();
    if (threadIdx.x < HEADS) {
        float bm = wvals[0][threadIdx.x];
#pragma unroll
        for (int w = 1; w < 8; w++) bm = fmaxf(bm, wvals[w][threadIdx.x]);
        g_blockmax[blockIdx.x * HEADS + threadIdx.x] = bm;
    }
}

// ---------------- 3: global max per head -----------------------------------
__global__ void reduce_max_kernel() {
    int h = blockIdx.x;
    __shared__ float sm[256];
    float m = -3.4e38f;
    for (int i = threadIdx.x; i < NODE_BLOCKS; i += 256)
        m = fmaxf(m, g_blockmax[i * HEADS + h]);
    sm[threadIdx.x] = m;
    __syncthreads();
    for (int s = 128; s > 0; s >>= 1) {
        if (threadIdx.x < s) sm[threadIdx.x] = fmaxf(sm[threadIdx.x], sm[threadIdx.x + s]);
        __syncthreads();
    }
    if (threadIdx.x == 0) g_max[h] = sm[0];
}

// ---------------- 4: exp (in place) + per-head sum -------------------------
__global__ void __launch_bounds__(256) coef_kernel() {
    __shared__ float ssum[HEADS];
    if (threadIdx.x < HEADS) ssum[threadIdx.x] = 0.f;
    __syncthreads();

    int e = blockIdx.x * 256 + threadIdx.x;
    float c0 = 0.f, c1 = 0.f, c2 = 0.f, c3 = 0.f;
    if (e < N_EDGES) {
        float4 l = *(float4*)&g_logit[(size_t)e * HEADS];
        c0 = __expf(l.x - g_max[0]);
        c1 = __expf(l.y - g_max[1]);
        c2 = __expf(l.z - g_max[2]);
        c3 = __expf(l.w - g_max[3]);
        *(float4*)&g_logit[(size_t)e * HEADS] = make_float4(c0, c1, c2, c3);
    }
#pragma unroll
    for (int m = 16; m > 0; m >>= 1) {
        c0 += __shfl_xor_sync(0xffffffffu, c0, m);
        c1 += __shfl_xor_sync(0xffffffffu, c1, m);
        c2 += __shfl_xor_sync(0xffffffffu, c2, m);
        c3 += __shfl_xor_sync(0xffffffffu, c3, m);
    }
    if ((threadIdx.x & 31) == 0) {
        atomicAdd(&ssum[0], c0);
        atomicAdd(&ssum[1], c1);
        atomicAdd(&ssum[2], c2);
        atomicAdd(&ssum[3], c3);
    }
    __syncthreads();
    if (threadIdx.x < HEADS) atomicAdd(&g_sum[threadIdx.x], ssum[threadIdx.x]);
}

// ---------------- 5: CSR aggregation (warp per node, no atomics) ------------
__global__ void __launch_bounds__(256) agg_csr_kernel() {
    int wid = threadIdx.x >> 5;
    int lane = threadIdx.x & 31;
    int n = blockIdx.x * 8 + wid;
    if (n >= N_PAD) return;

    int off0 = g_off[n];
    int off1 = g_off[n + 1];
    int h = lane >> 3;

    float4 a0 = make_float4(0.f, 0.f, 0.f, 0.f);
    float4 a1 = make_float4(0.f, 0.f, 0.f, 0.f);

#pragma unroll 2
    for (int i = off0; i < off1; i++) {
        int s = g_csr_src[i];
        float c = g_logit[(size_t)i * HEADS + h];
        const float4* v = (const float4*)(g_V + (size_t)s * QKVC) + lane * 2;
        float4 v0 = v[0], v1 = v[1];
        a0.x += c * v0.x; a0.y += c * v0.y; a0.z += c * v0.z; a0.w += c * v0.w;
        a1.x += c * v1.x; a1.y += c * v1.y; a1.z += c * v1.z; a1.w += c * v1.w;
    }

    float inv = 1.0f / g_sum[h];
    a0.x *= inv; a0.y *= inv; a0.z *= inv; a0.w *= inv;
    a1.x *= inv; a1.y *= inv; a1.z *= inv; a1.w *= inv;

    float4* dst = (float4*)(g_agg + (size_t)n * QKVC) + lane * 2;
    dst[0] = a0;
    dst[1] = a1;
}

// ---------------- 6: output GEMM (+bias), 64x64x16 -------------------------
__global__ void __launch_bounds__(256) out_gemm_kernel(
    const float* __restrict__ B, const float* __restrict__ bias,
    float* __restrict__ C)
{
    const int BM = 64, BK = 16;
    const int M = N_NODES, K = QKVC, NB = OUTC;
    __shared__ float As[BM][BK + 1];
    __shared__ float Bs[BK][68];

    int tid = threadIdx.x;
    int row0 = blockIdx.x * BM;
    int tx = tid & 15, ty = tid >> 4;

    float acc[4][4];
#pragma unroll
    for (int i = 0; i < 4; i++)
#pragma unroll
        for (int j = 0; j < 4; j++) acc[i][j] = 0.f;

    for (int k0 = 0; k0 < K; k0 += BK) {
        {
            int r = tid >> 2;
            int c4 = (tid & 3) * 4;
            int gr = row0 + r;
            float4 v = make_float4(0.f, 0.f, 0.f, 0.f);
            if (gr < M) v = *(const float4*)&g_agg[(size_t)gr * K + k0 + c4];
            As[r][c4 + 0] = v.x; As[r][c4 + 1] = v.y;
            As[r][c4 + 2] = v.z; As[r][c4 + 3] = v.w;
        }
        {
            int r = tid >> 4;
            int c4 = (tid & 15) * 4;
            float4 v = *(const float4*)&B[(size_t)(k0 + r) * NB + c4];
            Bs[r][c4 + 0] = v.x; Bs[r][c4 + 1] = v.y;
            Bs[r][c4 + 2] = v.z; Bs[r][c4 + 3] = v.w;
        }
        __syncthreads();
#pragma unroll
        for (int k = 0; k < BK; k++) {
            float ar[4], br[4];
#pragma unroll
            for (int i = 0; i < 4; i++) ar[i] = As[ty * 4 + i][k];
#pragma unroll
            for (int j = 0; j < 4; j++) br[j] = Bs[k][tx * 4 + j];
#pragma unroll
            for (int i = 0; i < 4; i++)
#pragma unroll
                for (int j = 0; j < 4; j++) acc[i][j] += ar[i] * br[j];
        }
        __syncthreads();
    }

#pragma unroll
    for (int i = 0; i < 4; i++) {
        int r = row0 + ty * 4 + i;
        if (r >= M) continue;
#pragma unroll
        for (int j = 0; j < 4; j++) {
            int c = tx * 4 + j;
            C[(size_t)r * NB + c] = acc[i][j] + bias[c];
        }
    }
}

// ---------------- launch ----------------------------------------------------
extern "C" void kernel_launch(void* const* d_in, const int* in_sizes, int n_in,
                              void* d_out, int out_size) {
    const float* x    = (const float*)d_in[0];
    const void*  ei   = d_in[1];
    const float* ew   = (const float*)d_in[2];
    const float* Wq   = (const float*)d_in[3];
    const float* Wk   = (const float*)d_in[4];
    const float* Wv   = (const float*)d_in[5];
    const float* We   = (const float*)d_in[6];
    const float* Wout = (const float*)d_in[7];
    const float* bout = (const float*)d_in[8];
    float* out = (float*)d_out;

    static bool init_done = false;
    static cudaStream_t sCsr = nullptr, sV = nullptr;
    static cudaEvent_t eRoot, ePrep, eCsr, eV;
    if (!init_done) {
        cudaFuncSetAttribute(qkv_wmma_kernel,
                             cudaFuncAttributeMaxDynamicSharedMemorySize, SM_QKV);
        cudaStreamCreateWithFlags(&sCsr, cudaStreamNonBlocking);
        cudaStreamCreateWithFlags(&sV,   cudaStreamNonBlocking);
        cudaEventCreateWithFlags(&eRoot, cudaEventDisableTiming);
        cudaEventCreateWithFlags(&ePrep, cudaEventDisableTiming);
        cudaEventCreateWithFlags(&eCsr,  cudaEventDisableTiming);
        cudaEventCreateWithFlags(&eV,    cudaEventDisableTiming);
        init_done = true;
    }

    // ---- main stream: sniff + zero (root of both branches) ----
    detect_idx_kernel<<<1, 32>>>((const int*)ei);
    zero_small_kernel<<<(N_PAD + 255) / 256, 256>>>();
    cudaEventRecord(eRoot, 0);

    // ---- fork: CSR build on side stream (independent of GEMMs) ----
    cudaStreamWaitEvent(sCsr, eRoot, 0);
    hist_kernel<<<(N_EDGES + 255) / 256, 256, 0, sCsr>>>(ei);
    scan_kernel<<<1, 1024, 0, sCsr>>>();
    scatter_kernel<<<(N_EDGES + 255) / 256, 256, 0, sCsr>>>(ei, ew);
    cudaEventRecord(eCsr, sCsr);

    // ---- main stream: operand prep + Q,K GEMM ----
    prep_x_kernel<<<(N_PAD * 16 + 255) / 256, 256>>>(x);
    prep_w_kernel<<<48, 256>>>(Wq, Wk, Wv);
    cudaEventRecord(ePrep, 0);

    dim3 qkgrid(M_TILES, 2, 2);
    qkv_wmma_kernel<<<qkgrid, 256, SM_QKV>>>(0);          // Q and K

    // ---- fork: V GEMM on side stream (overlaps logits/max/coef) ----
    cudaStreamWaitEvent(sV, ePrep, 0);
    dim3 vgrid(M_TILES, 2, 1);
    qkv_wmma_kernel<<<vgrid, 256, SM_QKV, sV>>>(2);       // V
    cudaEventRecord(eV, sV);

    // ---- main stream: edge phase (needs Q,K + CSR) ----
    cudaStreamWaitEvent(0, eCsr, 0);
    edge_logits_csr_kernel<<<NODE_BLOCKS, 256>>>(We);
    reduce_max_kernel<<<HEADS, 256>>>();
    coef_kernel<<<(N_EDGES + 255) / 256, 256>>>();

    // ---- join V, then aggregate + output ----
    cudaStreamWaitEvent(0, eV, 0);
    agg_csr_kernel<<<NODE_BLOCKS, 256>>>();
    out_gemm_kernel<<<N_PAD / 64, 256>>>(Wout, bout, out);
}